// round 12
// baseline (speedup 1.0000x reference)
#include <cuda_runtime.h>

// NavierStokesPINN1 — ReLU MLP is piecewise linear; outputs reduce to
//   u = dpsi/dy, v = -dpsi/dx, p, f = dp/dx, g = dp/dy.
// Forward pass reproduces the reference's fp32 rounding exactly (single acc,
// k ascending, fma per step, bias after reduction) so every ReLU mask matches.
// R12 = R9 skeleton (8 warps, WP8, grid 1024) with minimum-overhead loops:
//  - tables laid out [k][entries] (80B rows) -> LDS.128 broadcast fetches two
//    entries at once (4 loads/kl instead of 8)
//  - backward weights pre-DUPLICATED in gmem scratch ((w,w) pairs, lane-
//    contiguous) -> zero duplication movs in the backward hot loop
// Backward: 2 cotangent streams, point-pair packed, transposed weights.

#define H        256
#define NL       4
#define NPTS     65536
#define WP       8                  // points per warp
#define THREADS  256
#define WARPS    8
#define PTS_PER_CTA (WARPS * WP)    // 64
#define CHUNK_FLOATS 8192           // staging unit: 32KB (fwd 32 rows, bwd 16 rows)
#define NCHUNKS  96                 // 32 fwd + 64 bwd
#define TROW     10                 // table row stride in u64 (80B, 16B-aligned)

typedef unsigned long long u64;

// Backward weights, transposed AND duplicated: for layer l, row j (output
// neuron), 512 floats: blk b(0..3), lane, e(0..3):
//   value = Wh[l][k][j] with k = 128*(b>>1) + 4*lane + 2*(b&1) + (e>>1)
// so an LDS.128 at (j*512 + b*128 + lane*4) yields ((w_k0,w_k0),(w_k1,w_k1)).
__device__ float g_WhTd[2 * NL * H * H];

__device__ __forceinline__ u64 pack2(float lo, float hi) {
    u64 r; asm("mov.b64 %0, {%1, %2};" : "=l"(r) : "f"(lo), "f"(hi)); return r;
}
__device__ __forceinline__ void unpack2(u64 v, float& lo, float& hi) {
    asm("mov.b64 {%0, %1}, %2;" : "=f"(lo), "=f"(hi) : "l"(v));
}
__device__ __forceinline__ u64 ffma2(u64 a, u64 b, u64 c) {
    u64 d; asm("fma.rn.f32x2 %0, %1, %2, %3;" : "=l"(d) : "l"(a), "l"(b), "l"(c));
    return d;
}

__device__ __forceinline__ void cp_async16(void* s, const void* g) {
    unsigned sa = (unsigned)__cvta_generic_to_shared(s);
    asm volatile("cp.async.cg.shared.global [%0], [%1], 16;" :: "r"(sa), "l"(g));
}
__device__ __forceinline__ void cp_commit() { asm volatile("cp.async.commit_group;"); }
template<int NN> __device__ __forceinline__ void cp_wait() {
    asm volatile("cp.async.wait_group %0;" :: "n"(NN));
}

__device__ __forceinline__ void stage_chunk(float* dst, const float* src, int tid) {
    #pragma unroll
    for (int q = 0; q < CHUNK_FLOATS / 4 / THREADS; ++q) {   // 8 float4/thread
        int fi = q * THREADS + tid;
        cp_async16(((float4*)dst) + fi, ((const float4*)src) + fi);
    }
    cp_commit();
}

// chunks 0..31 = Wh layers 0..3 (forward, 32 rows each);
// chunks 32..95 = g_WhTd layers 3,2,1,0 (backward, 16 dup'd rows each).
__device__ __forceinline__ const float* chunk_src(int c, const float* Wh) {
    if (c < 32) return Wh + c * CHUNK_FLOATS;
    int cc = c - 32;                 // 0..63
    int bl = 3 - (cc >> 4);
    return g_WhTd + bl * (2 * H * H) + (cc & 15) * CHUNK_FLOATS;
}

__global__ void prep_kernel(const float* __restrict__ Wh) {
    int i = blockIdx.x * blockDim.x + threadIdx.x;   // 0 .. 2*NL*H*H-1
    int l   = i >> 17;
    int r2  = i & 131071;
    int j   = r2 >> 9;
    int col = r2 & 511;
    int b    = col >> 7;
    int lane = (col >> 2) & 31;
    int e    = col & 3;
    int k = ((b >> 1) << 7) + 4 * lane + ((b & 1) << 1) + (e >> 1);
    g_WhTd[i] = __ldg(Wh + (l << 16) + (k << 8) + j);
}

// lane owns neurons j = 128*(ln>>2) + 4*lane + (ln&3), ln = 0..7
#define JN(ln) ((((ln) >> 2) << 7) + (lane << 2) + ((ln) & 3))
// mask bit for (point pt 0..7, local neuron ln 0..7)
#define MB(pt, ln) ((u64)1 << (((pt) << 3) + (ln)))

__global__ void __launch_bounds__(THREADS, 1)
pinn_kernel(const float* __restrict__ x, const float* __restrict__ y,
            const float* __restrict__ t,
            const float* __restrict__ Win,  const float* __restrict__ b_in,
            const float* __restrict__ Wh,   const float* __restrict__ b_h,
            const float* __restrict__ Wout, const float* __restrict__ b_out,
            float* __restrict__ out)
{
    extern __shared__ float Ws[];   // [2][CHUNK_FLOATS] weights (64KB) + tables
    const int tid  = threadIdx.x;
    const int lane = tid & 31;
    const int warp = tid >> 5;
    const int base = blockIdx.x * PTS_PER_CTA + warp * WP;

    // per-warp table: 256 rows x TROW u64 (80B) = 20KB
    u64* tab = (u64*)(Ws + 2 * CHUNK_FLOATS) + (size_t)warp * (256 * TROW);
    // forward: tab[k*TROW + p]         = (h_p[k], h_p[k])  (duplicated)
    // backward: tab[k*TROW + 2q + s]   = (g_s[2q][k], g_s[2q+1][k])

    stage_chunk(Ws, chunk_src(0, Wh), tid);

    // ---------------- input layer (exact GEMM rounding order) ----------------
    u64 Mi = 0, Mh[NL];
    {
        float rx[WP], ry[WP], rt[WP];
        #pragma unroll
        for (int p = 0; p < WP; ++p) {
            rx[p] = x[base + p]; ry[p] = y[base + p]; rt[p] = t[base + p];
        }
        #pragma unroll
        for (int ln = 0; ln < 8; ++ln) {
            int j = JN(ln);
            float w0 = __ldg(Win + j);
            float w1 = __ldg(Win + H + j);
            float w2 = __ldg(Win + 2 * H + j);
            float bb = __ldg(b_in + j);
            #pragma unroll
            for (int p = 0; p < WP; ++p) {
                float acc = fmaf(rx[p], w0, 0.f);
                acc = fmaf(ry[p], w1, acc);
                acc = fmaf(rt[p], w2, acc);
                float a = acc + bb;
                bool m = a > 0.f;
                Mi |= m ? MB(p, ln) : 0ull;
                float hv = m ? a : 0.f;
                tab[j * TROW + p] = pack2(hv, hv);
            }
        }
    }
    __syncwarp();

    // ---------------- forward hidden layers ----------------
    float pp[WP];
    #pragma unroll
    for (int p = 0; p < WP; ++p) pp[p] = 0.f;
    int c = 0;

    #pragma unroll 1
    for (int l = 0; l < NL; ++l) {
        u64 acc[WP][4];             // [point][neuron-pair (2np, 2np+1)]
        #pragma unroll
        for (int p = 0; p < WP; ++p)
            #pragma unroll
            for (int np = 0; np < 4; ++np) acc[p][np] = 0ull;

        #pragma unroll 2
        for (int r = 0; r < 8; ++r, ++c) {
            stage_chunk(Ws + ((c + 1) & 1) * CHUNK_FLOATS, chunk_src(c + 1, Wh), tid);
            cp_wait<1>();
            __syncthreads();

            const float* wb = Ws + (c & 1) * CHUNK_FLOATS + (lane << 2);
            const u64* tf = tab + (r << 5) * TROW;
            #pragma unroll 4
            for (int kl = 0; kl < 32; ++kl) {
                ulonglong2 WA = *(const ulonglong2*)(wb + kl * H);        // (w0,w1),(w2,w3)
                ulonglong2 WB = *(const ulonglong2*)(wb + kl * H + 128);  // (w4,w5),(w6,w7)
                const ulonglong2* tr = (const ulonglong2*)(tf + kl * TROW);
                ulonglong2 T0 = tr[0];   // (h0,h0),(h1,h1)
                ulonglong2 T1 = tr[1];   // (h2,h2),(h3,h3)
                ulonglong2 T2 = tr[2];
                ulonglong2 T3 = tr[3];
                acc[0][0] = ffma2(T0.x, WA.x, acc[0][0]);
                acc[0][1] = ffma2(T0.x, WA.y, acc[0][1]);
                acc[0][2] = ffma2(T0.x, WB.x, acc[0][2]);
                acc[0][3] = ffma2(T0.x, WB.y, acc[0][3]);
                acc[1][0] = ffma2(T0.y, WA.x, acc[1][0]);
                acc[1][1] = ffma2(T0.y, WA.y, acc[1][1]);
                acc[1][2] = ffma2(T0.y, WB.x, acc[1][2]);
                acc[1][3] = ffma2(T0.y, WB.y, acc[1][3]);
                acc[2][0] = ffma2(T1.x, WA.x, acc[2][0]);
                acc[2][1] = ffma2(T1.x, WA.y, acc[2][1]);
                acc[2][2] = ffma2(T1.x, WB.x, acc[2][2]);
                acc[2][3] = ffma2(T1.x, WB.y, acc[2][3]);
                acc[3][0] = ffma2(T1.y, WA.x, acc[3][0]);
                acc[3][1] = ffma2(T1.y, WA.y, acc[3][1]);
                acc[3][2] = ffma2(T1.y, WB.x, acc[3][2]);
                acc[3][3] = ffma2(T1.y, WB.y, acc[3][3]);
                acc[4][0] = ffma2(T2.x, WA.x, acc[4][0]);
                acc[4][1] = ffma2(T2.x, WA.y, acc[4][1]);
                acc[4][2] = ffma2(T2.x, WB.x, acc[4][2]);
                acc[4][3] = ffma2(T2.x, WB.y, acc[4][3]);
                acc[5][0] = ffma2(T2.y, WA.x, acc[5][0]);
                acc[5][1] = ffma2(T2.y, WA.y, acc[5][1]);
                acc[5][2] = ffma2(T2.y, WB.x, acc[5][2]);
                acc[5][3] = ffma2(T2.y, WB.y, acc[5][3]);
                acc[6][0] = ffma2(T3.x, WA.x, acc[6][0]);
                acc[6][1] = ffma2(T3.x, WA.y, acc[6][1]);
                acc[6][2] = ffma2(T3.x, WB.x, acc[6][2]);
                acc[6][3] = ffma2(T3.x, WB.y, acc[6][3]);
                acc[7][0] = ffma2(T3.y, WA.x, acc[7][0]);
                acc[7][1] = ffma2(T3.y, WA.y, acc[7][1]);
                acc[7][2] = ffma2(T3.y, WB.x, acc[7][2]);
                acc[7][3] = ffma2(T3.y, WB.y, acc[7][3]);
            }
            __syncthreads();
        }

        // epilogue: bias AFTER reduction, relu, record mask
        u64 Ml = 0;
        #pragma unroll
        for (int np = 0; np < 4; ++np) {
            int ln0 = 2 * np;
            int j0 = JN(ln0);                 // j1 = j0 + 1
            float bb0 = __ldg(b_h + l * H + j0);
            float bb1 = __ldg(b_h + l * H + j0 + 1);
            if (l < NL - 1) {
                #pragma unroll
                for (int p = 0; p < WP; ++p) {
                    float a0, a1; unpack2(acc[p][np], a0, a1);
                    float v0 = a0 + bb0, v1 = a1 + bb1;
                    bool m0 = v0 > 0.f, m1 = v1 > 0.f;
                    Ml |= (m0 ? MB(p, ln0) : 0ull) | (m1 ? MB(p, ln0 + 1) : 0ull);
                    tab[j0 * TROW + p]       = pack2(m0 ? v0 : 0.f, m0 ? v0 : 0.f);
                    tab[(j0 + 1) * TROW + p] = pack2(m1 ? v1 : 0.f, m1 ? v1 : 0.f);
                }
            } else {
                float wo10 = __ldg(Wout + 2 * j0 + 1);
                float wo11 = __ldg(Wout + 2 * (j0 + 1) + 1);
                #pragma unroll
                for (int p = 0; p < WP; ++p) {
                    float a0, a1; unpack2(acc[p][np], a0, a1);
                    float v0 = a0 + bb0, v1 = a1 + bb1;
                    bool m0 = v0 > 0.f, m1 = v1 > 0.f;
                    Ml |= (m0 ? MB(p, ln0) : 0ull) | (m1 ? MB(p, ln0 + 1) : 0ull);
                    pp[p] = fmaf(m0 ? v0 : 0.f, wo10, pp[p]);
                    pp[p] = fmaf(m1 ? v1 : 0.f, wo11, pp[p]);
                }
            }
        }
        Mh[l] = Ml;
        __syncwarp();
    }

    // p output: warp-reduce and store
    #pragma unroll
    for (int off = 16; off > 0; off >>= 1)
        #pragma unroll
        for (int p = 0; p < WP; ++p)
            pp[p] += __shfl_xor_sync(0xffffffffu, pp[p], off);
    if (lane == 0) {
        float bo1 = __ldg(b_out + 1);
        #pragma unroll
        for (int p = 0; p < WP; ++p)
            out[2 * NPTS + base + p] = pp[p] + bo1;
    }

    // ---------------- backward init: masked layer-3 cotangents ----------------
    #pragma unroll
    for (int ln = 0; ln < 8; ++ln) {
        int j = JN(ln);
        float a0 = __ldg(Wout + 2 * j);       // psi stream
        float a1 = __ldg(Wout + 2 * j + 1);   // p stream
        #pragma unroll
        for (int q = 0; q < 4; ++q) {
            bool mlo = (Mh[3] & MB(2 * q, ln)) != 0ull;
            bool mhi = (Mh[3] & MB(2 * q + 1, ln)) != 0ull;
            tab[j * TROW + 2 * q]     = pack2(mlo ? a0 : 0.f, mhi ? a0 : 0.f);
            tab[j * TROW + 2 * q + 1] = pack2(mlo ? a1 : 0.f, mhi ? a1 : 0.f);
        }
    }
    __syncwarp();

    // ---------------- backward hidden layers ----------------
    u64 na0[4][8], na1[4][8];

    #pragma unroll 1
    for (int bl = 3; bl >= 0; --bl) {
        #pragma unroll
        for (int q = 0; q < 4; ++q)
            #pragma unroll
            for (int i = 0; i < 8; ++i) { na0[q][i] = 0ull; na1[q][i] = 0ull; }

        #pragma unroll 2
        for (int r = 0; r < 16; ++r, ++c) {
            if (c + 1 < NCHUNKS) {
                stage_chunk(Ws + ((c + 1) & 1) * CHUNK_FLOATS, chunk_src(c + 1, Wh), tid);
                cp_wait<1>();
            } else {
                cp_wait<0>();
            }
            __syncthreads();

            const float* wb = Ws + (c & 1) * CHUNK_FLOATS + (lane << 2);
            const u64* tbb = tab + (r << 4) * TROW;
            #pragma unroll 4
            for (int kl = 0; kl < 16; ++kl) {
                const float* wr = wb + kl * 512;
                ulonglong2 W0 = *(const ulonglong2*)(wr);        // (wk0,wk0),(wk1,wk1)
                ulonglong2 W1 = *(const ulonglong2*)(wr + 128);  // ln2, ln3
                ulonglong2 W2 = *(const ulonglong2*)(wr + 256);  // ln4, ln5
                ulonglong2 W3 = *(const ulonglong2*)(wr + 384);  // ln6, ln7
                const ulonglong2* tr = (const ulonglong2*)(tbb + kl * TROW);
                ulonglong2 B0 = tr[0];   // .x = psi pts(0,1), .y = p pts(0,1)
                ulonglong2 B1 = tr[1];
                ulonglong2 B2 = tr[2];
                ulonglong2 B3 = tr[3];
                na0[0][0] = ffma2(B0.x, W0.x, na0[0][0]);
                na0[0][1] = ffma2(B0.x, W0.y, na0[0][1]);
                na0[0][2] = ffma2(B0.x, W1.x, na0[0][2]);
                na0[0][3] = ffma2(B0.x, W1.y, na0[0][3]);
                na0[0][4] = ffma2(B0.x, W2.x, na0[0][4]);
                na0[0][5] = ffma2(B0.x, W2.y, na0[0][5]);
                na0[0][6] = ffma2(B0.x, W3.x, na0[0][6]);
                na0[0][7] = ffma2(B0.x, W3.y, na0[0][7]);
                na1[0][0] = ffma2(B0.y, W0.x, na1[0][0]);
                na1[0][1] = ffma2(B0.y, W0.y, na1[0][1]);
                na1[0][2] = ffma2(B0.y, W1.x, na1[0][2]);
                na1[0][3] = ffma2(B0.y, W1.y, na1[0][3]);
                na1[0][4] = ffma2(B0.y, W2.x, na1[0][4]);
                na1[0][5] = ffma2(B0.y, W2.y, na1[0][5]);
                na1[0][6] = ffma2(B0.y, W3.x, na1[0][6]);
                na1[0][7] = ffma2(B0.y, W3.y, na1[0][7]);
                na0[1][0] = ffma2(B1.x, W0.x, na0[1][0]);
                na0[1][1] = ffma2(B1.x, W0.y, na0[1][1]);
                na0[1][2] = ffma2(B1.x, W1.x, na0[1][2]);
                na0[1][3] = ffma2(B1.x, W1.y, na0[1][3]);
                na0[1][4] = ffma2(B1.x, W2.x, na0[1][4]);
                na0[1][5] = ffma2(B1.x, W2.y, na0[1][5]);
                na0[1][6] = ffma2(B1.x, W3.x, na0[1][6]);
                na0[1][7] = ffma2(B1.x, W3.y, na0[1][7]);
                na1[1][0] = ffma2(B1.y, W0.x, na1[1][0]);
                na1[1][1] = ffma2(B1.y, W0.y, na1[1][1]);
                na1[1][2] = ffma2(B1.y, W1.x, na1[1][2]);
                na1[1][3] = ffma2(B1.y, W1.y, na1[1][3]);
                na1[1][4] = ffma2(B1.y, W2.x, na1[1][4]);
                na1[1][5] = ffma2(B1.y, W2.y, na1[1][5]);
                na1[1][6] = ffma2(B1.y, W3.x, na1[1][6]);
                na1[1][7] = ffma2(B1.y, W3.y, na1[1][7]);
                na0[2][0] = ffma2(B2.x, W0.x, na0[2][0]);
                na0[2][1] = ffma2(B2.x, W0.y, na0[2][1]);
                na0[2][2] = ffma2(B2.x, W1.x, na0[2][2]);
                na0[2][3] = ffma2(B2.x, W1.y, na0[2][3]);
                na0[2][4] = ffma2(B2.x, W2.x, na0[2][4]);
                na0[2][5] = ffma2(B2.x, W2.y, na0[2][5]);
                na0[2][6] = ffma2(B2.x, W3.x, na0[2][6]);
                na0[2][7] = ffma2(B2.x, W3.y, na0[2][7]);
                na1[2][0] = ffma2(B2.y, W0.x, na1[2][0]);
                na1[2][1] = ffma2(B2.y, W0.y, na1[2][1]);
                na1[2][2] = ffma2(B2.y, W1.x, na1[2][2]);
                na1[2][3] = ffma2(B2.y, W1.y, na1[2][3]);
                na1[2][4] = ffma2(B2.y, W2.x, na1[2][4]);
                na1[2][5] = ffma2(B2.y, W2.y, na1[2][5]);
                na1[2][6] = ffma2(B2.y, W3.x, na1[2][6]);
                na1[2][7] = ffma2(B2.y, W3.y, na1[2][7]);
                na0[3][0] = ffma2(B3.x, W0.x, na0[3][0]);
                na0[3][1] = ffma2(B3.x, W0.y, na0[3][1]);
                na0[3][2] = ffma2(B3.x, W1.x, na0[3][2]);
                na0[3][3] = ffma2(B3.x, W1.y, na0[3][3]);
                na0[3][4] = ffma2(B3.x, W2.x, na0[3][4]);
                na0[3][5] = ffma2(B3.x, W2.y, na0[3][5]);
                na0[3][6] = ffma2(B3.x, W3.x, na0[3][6]);
                na0[3][7] = ffma2(B3.x, W3.y, na0[3][7]);
                na1[3][0] = ffma2(B3.y, W0.x, na1[3][0]);
                na1[3][1] = ffma2(B3.y, W0.y, na1[3][1]);
                na1[3][2] = ffma2(B3.y, W1.x, na1[3][2]);
                na1[3][3] = ffma2(B3.y, W1.y, na1[3][3]);
                na1[3][4] = ffma2(B3.y, W2.x, na1[3][4]);
                na1[3][5] = ffma2(B3.y, W2.y, na1[3][5]);
                na1[3][6] = ffma2(B3.y, W3.x, na1[3][6]);
                na1[3][7] = ffma2(B3.y, W3.y, na1[3][7]);
            }
            __syncthreads();
        }

        if (bl > 0) {   // mask by previous layer, refill tables
            u64 Mp = Mh[bl - 1];
            #pragma unroll
            for (int ln = 0; ln < 8; ++ln) {
                int j = JN(ln);
                #pragma unroll
                for (int q = 0; q < 4; ++q) {
                    bool mlo = (Mp & MB(2 * q, ln)) != 0ull;
                    bool mhi = (Mp & MB(2 * q + 1, ln)) != 0ull;
                    float l0, h0, l1, h1;
                    unpack2(na0[q][ln], l0, h0);
                    unpack2(na1[q][ln], l1, h1);
                    tab[j * TROW + 2 * q]     = pack2(mlo ? l0 : 0.f, mhi ? h0 : 0.f);
                    tab[j * TROW + 2 * q + 1] = pack2(mlo ? l1 : 0.f, mhi ? h1 : 0.f);
                }
            }
            __syncwarp();
        }
    }

    // ---------------- input-layer backward + outputs ----------------
    float su[WP], sv[WP], sf[WP], sg[WP];
    #pragma unroll
    for (int p = 0; p < WP; ++p) { su[p] = sv[p] = sf[p] = sg[p] = 0.f; }

    #pragma unroll
    for (int ln = 0; ln < 8; ++ln) {
        int j = JN(ln);
        float wx = __ldg(Win + j);
        float wy = __ldg(Win + H + j);
        #pragma unroll
        for (int q = 0; q < 4; ++q) {
            float g0[2], g1[2];
            unpack2(na0[q][ln], g0[0], g0[1]);
            unpack2(na1[q][ln], g1[0], g1[1]);
            #pragma unroll
            for (int hh = 0; hh < 2; ++hh) {
                int p = 2 * q + hh;
                bool m = (Mi & MB(p, ln)) != 0ull;
                float r0 = m ? g0[hh] : 0.f;
                float r1 = m ? g1[hh] : 0.f;
                su[p] = fmaf(wy, r0, su[p]);
                sv[p] = fmaf(wx, r0, sv[p]);
                sf[p] = fmaf(wx, r1, sf[p]);
                sg[p] = fmaf(wy, r1, sg[p]);
            }
        }
    }

    #pragma unroll
    for (int off = 16; off > 0; off >>= 1) {
        #pragma unroll
        for (int p = 0; p < WP; ++p) {
            su[p] += __shfl_xor_sync(0xffffffffu, su[p], off);
            sv[p] += __shfl_xor_sync(0xffffffffu, sv[p], off);
            sf[p] += __shfl_xor_sync(0xffffffffu, sf[p], off);
            sg[p] += __shfl_xor_sync(0xffffffffu, sg[p], off);
        }
    }
    if (lane == 0) {
        #pragma unroll
        for (int p = 0; p < WP; ++p) {
            int pt = base + p;
            out[0 * NPTS + pt] =  su[p];
            out[1 * NPTS + pt] = -sv[p];
            out[3 * NPTS + pt] =  sf[p];
            out[4 * NPTS + pt] =  sg[p];
        }
    }
}

extern "C" void kernel_launch(void* const* d_in, const int* in_sizes, int n_in,
                              void* d_out, int out_size)
{
    const float* x     = (const float*)d_in[0];
    const float* y     = (const float*)d_in[1];
    const float* t     = (const float*)d_in[2];
    const float* Win   = (const float*)d_in[3];
    const float* b_in  = (const float*)d_in[4];
    const float* Wh    = (const float*)d_in[5];
    const float* b_h   = (const float*)d_in[6];
    const float* Wout  = (const float*)d_in[7];
    const float* b_out = (const float*)d_in[8];
    float* out = (float*)d_out;

    prep_kernel<<<(2 * NL * H * H) / 256, 256>>>(Wh);

    // 64KB weight double-buffer + 8 warps * 20KB tables = 224KB
    const int smem = 2 * CHUNK_FLOATS * (int)sizeof(float)
                   + WARPS * (256 * TROW) * (int)sizeof(u64);
    cudaFuncSetAttribute(pinn_kernel, cudaFuncAttributeMaxDynamicSharedMemorySize, smem);
    pinn_kernel<<<NPTS / PTS_PER_CTA, THREADS, smem>>>(x, y, t, Win, b_in, Wh, b_h,
                                                       Wout, b_out, out);
}

// round 13
// speedup vs baseline: 1.0921x; 1.0921x over previous
#include <cuda_runtime.h>

// NavierStokesPINN1 — ReLU MLP is piecewise linear; outputs reduce to
//   u = dpsi/dy, v = -dpsi/dx, p, f = dp/dx, g = dp/dy.
// Forward pass reproduces the reference's fp32 rounding exactly (single acc,
// k ascending, fma per step, bias after reduction) so every ReLU mask matches.
// R13 = R9 math/chunk schedule with:
//  - triple-buffered weight staging -> ONE __syncthreads per chunk (64 vs 128)
//  - [k]-row 64B table layout -> 4x LDS.128 broadcasts per kl (was 8x LDS.64)
// Backward: 2 cotangent streams, point-pair packed, transposed weights,
// 32 non-duplicated chunks (FMA density per chunk unchanged vs R9).

#define H        256
#define NL       4
#define NPTS     65536
#define WP       8                  // points per warp
#define THREADS  256
#define WARPS    8
#define PTS_PER_CTA (WARPS * WP)    // 64
#define CHUNK    32
#define CHUNK_FLOATS (CHUNK * H)    // 8192 floats = 32KB
#define NBUF     3
#define NCHUNKS  64
#define TROWU    8                  // table row stride in u64 (64B)

typedef unsigned long long u64;

__device__ float g_WhT[NL * H * H];   // transposed hidden weights (backward)

__device__ __forceinline__ u64 pack2(float lo, float hi) {
    u64 r; asm("mov.b64 %0, {%1, %2};" : "=l"(r) : "f"(lo), "f"(hi)); return r;
}
__device__ __forceinline__ void unpack2(u64 v, float& lo, float& hi) {
    asm("mov.b64 {%0, %1}, %2;" : "=f"(lo), "=f"(hi) : "l"(v));
}
__device__ __forceinline__ u64 ffma2(u64 a, u64 b, u64 c) {
    u64 d; asm("fma.rn.f32x2 %0, %1, %2, %3;" : "=l"(d) : "l"(a), "l"(b), "l"(c));
    return d;
}

__device__ __forceinline__ void cp_async16(void* s, const void* g) {
    unsigned sa = (unsigned)__cvta_generic_to_shared(s);
    asm volatile("cp.async.cg.shared.global [%0], [%1], 16;" :: "r"(sa), "l"(g));
}
__device__ __forceinline__ void cp_commit() { asm volatile("cp.async.commit_group;"); }
template<int NN> __device__ __forceinline__ void cp_wait() {
    asm volatile("cp.async.wait_group %0;" :: "n"(NN));
}

__device__ __forceinline__ void stage_chunk(float* dst, const float* src, int tid) {
    #pragma unroll
    for (int q = 0; q < CHUNK_FLOATS / 4 / THREADS; ++q) {   // 8 float4/thread
        int fi = q * THREADS + tid;
        cp_async16(((float4*)dst) + fi, ((const float4*)src) + fi);
    }
    cp_commit();
}

// chunks 0..31 = Wh layers 0..3 (forward), 32..63 = g_WhT layers 3,2,1,0.
__device__ __forceinline__ const float* chunk_src(int c, const float* Wh) {
    if (c < 32) return Wh + c * CHUNK_FLOATS;
    int cc = c - 32;
    int l = 3 - (cc >> 3);
    return g_WhT + (l << 16) + (cc & 7) * CHUNK_FLOATS;
}

__global__ void prep_kernel(const float* __restrict__ Wh) {
    int i = blockIdx.x * blockDim.x + threadIdx.x;
    float v = __ldg(Wh + i);
    int l = i >> 16;
    int rem = i & 0xFFFF;
    int k = rem >> 8, j = rem & 0xFF;
    g_WhT[(l << 16) + (j << 8) + k] = v;
}

// lane owns neurons j = 128*(ln>>2) + 4*lane + (ln&3), ln = 0..7
#define JN(ln) ((((ln) >> 2) << 7) + (lane << 2) + ((ln) & 3))
// mask bit for (point pt 0..7, local neuron ln 0..7)
#define MB(pt, ln) ((u64)1 << (((pt) << 3) + (ln)))

__global__ void __launch_bounds__(THREADS, 1)
pinn_kernel(const float* __restrict__ x, const float* __restrict__ y,
            const float* __restrict__ t,
            const float* __restrict__ Win,  const float* __restrict__ b_in,
            const float* __restrict__ Wh,   const float* __restrict__ b_h,
            const float* __restrict__ Wout, const float* __restrict__ b_out,
            float* __restrict__ out)
{
    extern __shared__ float Ws[];   // [NBUF][CHUNK_FLOATS] weights (96KB) + tables
    const int tid  = threadIdx.x;
    const int lane = tid & 31;
    const int warp = tid >> 5;
    const int base = blockIdx.x * PTS_PER_CTA + warp * WP;

    // per-warp table: 256 rows x TROWU u64 (64B rows) = 16KB
    // forward:  tab[k*TROWU + p]       = (h_p[k], h_p[k])      (duplicated)
    // backward: tab[j*TROWU + 2q + s]  = stream s, point-pair q = (g[2q], g[2q+1])
    u64* tab = (u64*)(Ws + NBUF * CHUNK_FLOATS) + (size_t)warp * (256 * TROWU);

    stage_chunk(Ws, chunk_src(0, Wh), tid);

    // ---------------- input layer (exact GEMM rounding order) ----------------
    u64 Mi = 0, Mh[NL];
    {
        float rx[WP], ry[WP], rt[WP];
        #pragma unroll
        for (int p = 0; p < WP; ++p) {
            rx[p] = x[base + p]; ry[p] = y[base + p]; rt[p] = t[base + p];
        }
        #pragma unroll
        for (int ln = 0; ln < 8; ++ln) {
            int j = JN(ln);
            float w0 = __ldg(Win + j);
            float w1 = __ldg(Win + H + j);
            float w2 = __ldg(Win + 2 * H + j);
            float bb = __ldg(b_in + j);
            #pragma unroll
            for (int p = 0; p < WP; ++p) {
                float acc = fmaf(rx[p], w0, 0.f);
                acc = fmaf(ry[p], w1, acc);
                acc = fmaf(rt[p], w2, acc);
                float a = acc + bb;
                bool m = a > 0.f;
                Mi |= m ? MB(p, ln) : 0ull;
                float hv = m ? a : 0.f;
                tab[j * TROWU + p] = pack2(hv, hv);
            }
        }
    }
    __syncwarp();

    // ---------------- forward hidden layers ----------------
    float pp[WP];
    #pragma unroll
    for (int p = 0; p < WP; ++p) pp[p] = 0.f;
    int c = 0;

    #pragma unroll 1
    for (int l = 0; l < NL; ++l) {
        u64 acc[WP][4];             // [point][neuron-pair (2np, 2np+1)]
        #pragma unroll
        for (int p = 0; p < WP; ++p)
            #pragma unroll
            for (int np = 0; np < 4; ++np) acc[p][np] = 0ull;

        #pragma unroll 2
        for (int r = 0; r < 8; ++r, ++c) {
            if (c + 1 < NCHUNKS) {
                stage_chunk(Ws + ((c + 1) % NBUF) * CHUNK_FLOATS, chunk_src(c + 1, Wh), tid);
                cp_wait<1>();
            } else {
                cp_wait<0>();
            }
            __syncthreads();        // single barrier per chunk (triple buffer)

            const float* wb = Ws + (c % NBUF) * CHUNK_FLOATS + (lane << 2);
            const u64* tf = tab + (r << 5) * TROWU;
            #pragma unroll 4
            for (int kl = 0; kl < CHUNK; ++kl) {
                ulonglong2 WA = *(const ulonglong2*)(wb + kl * H);        // (w0,w1),(w2,w3)
                ulonglong2 WB = *(const ulonglong2*)(wb + kl * H + 128);  // (w4,w5),(w6,w7)
                const ulonglong2* tr = (const ulonglong2*)(tf + kl * TROWU);
                ulonglong2 T0 = tr[0];   // (h0,h0),(h1,h1)
                ulonglong2 T1 = tr[1];
                ulonglong2 T2 = tr[2];
                ulonglong2 T3 = tr[3];
                acc[0][0] = ffma2(T0.x, WA.x, acc[0][0]);
                acc[0][1] = ffma2(T0.x, WA.y, acc[0][1]);
                acc[0][2] = ffma2(T0.x, WB.x, acc[0][2]);
                acc[0][3] = ffma2(T0.x, WB.y, acc[0][3]);
                acc[1][0] = ffma2(T0.y, WA.x, acc[1][0]);
                acc[1][1] = ffma2(T0.y, WA.y, acc[1][1]);
                acc[1][2] = ffma2(T0.y, WB.x, acc[1][2]);
                acc[1][3] = ffma2(T0.y, WB.y, acc[1][3]);
                acc[2][0] = ffma2(T1.x, WA.x, acc[2][0]);
                acc[2][1] = ffma2(T1.x, WA.y, acc[2][1]);
                acc[2][2] = ffma2(T1.x, WB.x, acc[2][2]);
                acc[2][3] = ffma2(T1.x, WB.y, acc[2][3]);
                acc[3][0] = ffma2(T1.y, WA.x, acc[3][0]);
                acc[3][1] = ffma2(T1.y, WA.y, acc[3][1]);
                acc[3][2] = ffma2(T1.y, WB.x, acc[3][2]);
                acc[3][3] = ffma2(T1.y, WB.y, acc[3][3]);
                acc[4][0] = ffma2(T2.x, WA.x, acc[4][0]);
                acc[4][1] = ffma2(T2.x, WA.y, acc[4][1]);
                acc[4][2] = ffma2(T2.x, WB.x, acc[4][2]);
                acc[4][3] = ffma2(T2.x, WB.y, acc[4][3]);
                acc[5][0] = ffma2(T2.y, WA.x, acc[5][0]);
                acc[5][1] = ffma2(T2.y, WA.y, acc[5][1]);
                acc[5][2] = ffma2(T2.y, WB.x, acc[5][2]);
                acc[5][3] = ffma2(T2.y, WB.y, acc[5][3]);
                acc[6][0] = ffma2(T3.x, WA.x, acc[6][0]);
                acc[6][1] = ffma2(T3.x, WA.y, acc[6][1]);
                acc[6][2] = ffma2(T3.x, WB.x, acc[6][2]);
                acc[6][3] = ffma2(T3.x, WB.y, acc[6][3]);
                acc[7][0] = ffma2(T3.y, WA.x, acc[7][0]);
                acc[7][1] = ffma2(T3.y, WA.y, acc[7][1]);
                acc[7][2] = ffma2(T3.y, WB.x, acc[7][2]);
                acc[7][3] = ffma2(T3.y, WB.y, acc[7][3]);
            }
        }

        // epilogue: bias AFTER reduction, relu, record mask
        u64 Ml = 0;
        #pragma unroll
        for (int np = 0; np < 4; ++np) {
            int ln0 = 2 * np;
            int j0 = JN(ln0);                 // j1 = j0 + 1
            float bb0 = __ldg(b_h + l * H + j0);
            float bb1 = __ldg(b_h + l * H + j0 + 1);
            if (l < NL - 1) {
                #pragma unroll
                for (int p = 0; p < WP; ++p) {
                    float a0, a1; unpack2(acc[p][np], a0, a1);
                    float v0 = a0 + bb0, v1 = a1 + bb1;
                    bool m0 = v0 > 0.f, m1 = v1 > 0.f;
                    Ml |= (m0 ? MB(p, ln0) : 0ull) | (m1 ? MB(p, ln0 + 1) : 0ull);
                    tab[j0 * TROWU + p]       = pack2(m0 ? v0 : 0.f, m0 ? v0 : 0.f);
                    tab[(j0 + 1) * TROWU + p] = pack2(m1 ? v1 : 0.f, m1 ? v1 : 0.f);
                }
            } else {
                float wo10 = __ldg(Wout + 2 * j0 + 1);
                float wo11 = __ldg(Wout + 2 * (j0 + 1) + 1);
                #pragma unroll
                for (int p = 0; p < WP; ++p) {
                    float a0, a1; unpack2(acc[p][np], a0, a1);
                    float v0 = a0 + bb0, v1 = a1 + bb1;
                    bool m0 = v0 > 0.f, m1 = v1 > 0.f;
                    Ml |= (m0 ? MB(p, ln0) : 0ull) | (m1 ? MB(p, ln0 + 1) : 0ull);
                    pp[p] = fmaf(m0 ? v0 : 0.f, wo10, pp[p]);
                    pp[p] = fmaf(m1 ? v1 : 0.f, wo11, pp[p]);
                }
            }
        }
        Mh[l] = Ml;
        __syncwarp();
    }

    // p output: warp-reduce and store
    #pragma unroll
    for (int off = 16; off > 0; off >>= 1)
        #pragma unroll
        for (int p = 0; p < WP; ++p)
            pp[p] += __shfl_xor_sync(0xffffffffu, pp[p], off);
    if (lane == 0) {
        float bo1 = __ldg(b_out + 1);
        #pragma unroll
        for (int p = 0; p < WP; ++p)
            out[2 * NPTS + base + p] = pp[p] + bo1;
    }

    // ---------------- backward init: masked layer-3 cotangents ----------------
    #pragma unroll
    for (int ln = 0; ln < 8; ++ln) {
        int j = JN(ln);
        float a0 = __ldg(Wout + 2 * j);       // psi stream
        float a1 = __ldg(Wout + 2 * j + 1);   // p stream
        #pragma unroll
        for (int q = 0; q < 4; ++q) {
            bool mlo = (Mh[3] & MB(2 * q, ln)) != 0ull;
            bool mhi = (Mh[3] & MB(2 * q + 1, ln)) != 0ull;
            tab[j * TROWU + 2 * q]     = pack2(mlo ? a0 : 0.f, mhi ? a0 : 0.f);
            tab[j * TROWU + 2 * q + 1] = pack2(mlo ? a1 : 0.f, mhi ? a1 : 0.f);
        }
    }
    __syncwarp();

    // ---------------- backward hidden layers (point-pair packing) ----------------
    u64 na0[4][8], na1[4][8];

    #pragma unroll 1
    for (int bl = 3; bl >= 0; --bl) {
        #pragma unroll
        for (int q = 0; q < 4; ++q)
            #pragma unroll
            for (int i = 0; i < 8; ++i) { na0[q][i] = 0ull; na1[q][i] = 0ull; }

        #pragma unroll 2
        for (int r = 0; r < 8; ++r, ++c) {
            if (c + 1 < NCHUNKS) {
                stage_chunk(Ws + ((c + 1) % NBUF) * CHUNK_FLOATS, chunk_src(c + 1, Wh), tid);
                cp_wait<1>();
            } else {
                cp_wait<0>();
            }
            __syncthreads();        // single barrier per chunk

            const float* wb = Ws + (c % NBUF) * CHUNK_FLOATS + (lane << 2);
            const u64* tbb = tab + (r << 5) * TROWU;
            #pragma unroll 4
            for (int kl = 0; kl < CHUNK; ++kl) {
                float4 wA = *(const float4*)(wb + kl * H);
                float4 wB = *(const float4*)(wb + kl * H + 128);
                u64 w0 = pack2(wA.x, wA.x), w1 = pack2(wA.y, wA.y);
                u64 w2 = pack2(wA.z, wA.z), w3 = pack2(wA.w, wA.w);
                u64 w4 = pack2(wB.x, wB.x), w5 = pack2(wB.y, wB.y);
                u64 w6 = pack2(wB.z, wB.z), w7 = pack2(wB.w, wB.w);
                const ulonglong2* tr = (const ulonglong2*)(tbb + kl * TROWU);
                ulonglong2 B0 = tr[0];   // .x = psi pair q0, .y = p pair q0
                ulonglong2 B1 = tr[1];
                ulonglong2 B2 = tr[2];
                ulonglong2 B3 = tr[3];
                na0[0][0] = ffma2(B0.x, w0, na0[0][0]);
                na0[0][1] = ffma2(B0.x, w1, na0[0][1]);
                na0[0][2] = ffma2(B0.x, w2, na0[0][2]);
                na0[0][3] = ffma2(B0.x, w3, na0[0][3]);
                na0[0][4] = ffma2(B0.x, w4, na0[0][4]);
                na0[0][5] = ffma2(B0.x, w5, na0[0][5]);
                na0[0][6] = ffma2(B0.x, w6, na0[0][6]);
                na0[0][7] = ffma2(B0.x, w7, na0[0][7]);
                na1[0][0] = ffma2(B0.y, w0, na1[0][0]);
                na1[0][1] = ffma2(B0.y, w1, na1[0][1]);
                na1[0][2] = ffma2(B0.y, w2, na1[0][2]);
                na1[0][3] = ffma2(B0.y, w3, na1[0][3]);
                na1[0][4] = ffma2(B0.y, w4, na1[0][4]);
                na1[0][5] = ffma2(B0.y, w5, na1[0][5]);
                na1[0][6] = ffma2(B0.y, w6, na1[0][6]);
                na1[0][7] = ffma2(B0.y, w7, na1[0][7]);
                na0[1][0] = ffma2(B1.x, w0, na0[1][0]);
                na0[1][1] = ffma2(B1.x, w1, na0[1][1]);
                na0[1][2] = ffma2(B1.x, w2, na0[1][2]);
                na0[1][3] = ffma2(B1.x, w3, na0[1][3]);
                na0[1][4] = ffma2(B1.x, w4, na0[1][4]);
                na0[1][5] = ffma2(B1.x, w5, na0[1][5]);
                na0[1][6] = ffma2(B1.x, w6, na0[1][6]);
                na0[1][7] = ffma2(B1.x, w7, na0[1][7]);
                na1[1][0] = ffma2(B1.y, w0, na1[1][0]);
                na1[1][1] = ffma2(B1.y, w1, na1[1][1]);
                na1[1][2] = ffma2(B1.y, w2, na1[1][2]);
                na1[1][3] = ffma2(B1.y, w3, na1[1][3]);
                na1[1][4] = ffma2(B1.y, w4, na1[1][4]);
                na1[1][5] = ffma2(B1.y, w5, na1[1][5]);
                na1[1][6] = ffma2(B1.y, w6, na1[1][6]);
                na1[1][7] = ffma2(B1.y, w7, na1[1][7]);
                na0[2][0] = ffma2(B2.x, w0, na0[2][0]);
                na0[2][1] = ffma2(B2.x, w1, na0[2][1]);
                na0[2][2] = ffma2(B2.x, w2, na0[2][2]);
                na0[2][3] = ffma2(B2.x, w3, na0[2][3]);
                na0[2][4] = ffma2(B2.x, w4, na0[2][4]);
                na0[2][5] = ffma2(B2.x, w5, na0[2][5]);
                na0[2][6] = ffma2(B2.x, w6, na0[2][6]);
                na0[2][7] = ffma2(B2.x, w7, na0[2][7]);
                na1[2][0] = ffma2(B2.y, w0, na1[2][0]);
                na1[2][1] = ffma2(B2.y, w1, na1[2][1]);
                na1[2][2] = ffma2(B2.y, w2, na1[2][2]);
                na1[2][3] = ffma2(B2.y, w3, na1[2][3]);
                na1[2][4] = ffma2(B2.y, w4, na1[2][4]);
                na1[2][5] = ffma2(B2.y, w5, na1[2][5]);
                na1[2][6] = ffma2(B2.y, w6, na1[2][6]);
                na1[2][7] = ffma2(B2.y, w7, na1[2][7]);
                na0[3][0] = ffma2(B3.x, w0, na0[3][0]);
                na0[3][1] = ffma2(B3.x, w1, na0[3][1]);
                na0[3][2] = ffma2(B3.x, w2, na0[3][2]);
                na0[3][3] = ffma2(B3.x, w3, na0[3][3]);
                na0[3][4] = ffma2(B3.x, w4, na0[3][4]);
                na0[3][5] = ffma2(B3.x, w5, na0[3][5]);
                na0[3][6] = ffma2(B3.x, w6, na0[3][6]);
                na0[3][7] = ffma2(B3.x, w7, na0[3][7]);
                na1[3][0] = ffma2(B3.y, w0, na1[3][0]);
                na1[3][1] = ffma2(B3.y, w1, na1[3][1]);
                na1[3][2] = ffma2(B3.y, w2, na1[3][2]);
                na1[3][3] = ffma2(B3.y, w3, na1[3][3]);
                na1[3][4] = ffma2(B3.y, w4, na1[3][4]);
                na1[3][5] = ffma2(B3.y, w5, na1[3][5]);
                na1[3][6] = ffma2(B3.y, w6, na1[3][6]);
                na1[3][7] = ffma2(B3.y, w7, na1[3][7]);
            }
        }

        if (bl > 0) {   // mask by previous layer, refill tables
            u64 Mp = Mh[bl - 1];
            #pragma unroll
            for (int ln = 0; ln < 8; ++ln) {
                int j = JN(ln);
                #pragma unroll
                for (int q = 0; q < 4; ++q) {
                    bool mlo = (Mp & MB(2 * q, ln)) != 0ull;
                    bool mhi = (Mp & MB(2 * q + 1, ln)) != 0ull;
                    float l0, h0, l1, h1;
                    unpack2(na0[q][ln], l0, h0);
                    unpack2(na1[q][ln], l1, h1);
                    tab[j * TROWU + 2 * q]     = pack2(mlo ? l0 : 0.f, mhi ? h0 : 0.f);
                    tab[j * TROWU + 2 * q + 1] = pack2(mlo ? l1 : 0.f, mhi ? h1 : 0.f);
                }
            }
            __syncwarp();
        }
    }

    // ---------------- input-layer backward + outputs ----------------
    float su[WP], sv[WP], sf[WP], sg[WP];
    #pragma unroll
    for (int p = 0; p < WP; ++p) { su[p] = sv[p] = sf[p] = sg[p] = 0.f; }

    #pragma unroll
    for (int ln = 0; ln < 8; ++ln) {
        int j = JN(ln);
        float wx = __ldg(Win + j);
        float wy = __ldg(Win + H + j);
        #pragma unroll
        for (int q = 0; q < 4; ++q) {
            float g0[2], g1[2];
            unpack2(na0[q][ln], g0[0], g0[1]);
            unpack2(na1[q][ln], g1[0], g1[1]);
            #pragma unroll
            for (int hh = 0; hh < 2; ++hh) {
                int p = 2 * q + hh;
                bool m = (Mi & MB(p, ln)) != 0ull;
                float r0 = m ? g0[hh] : 0.f;
                float r1 = m ? g1[hh] : 0.f;
                su[p] = fmaf(wy, r0, su[p]);
                sv[p] = fmaf(wx, r0, sv[p]);
                sf[p] = fmaf(wx, r1, sf[p]);
                sg[p] = fmaf(wy, r1, sg[p]);
            }
        }
    }

    #pragma unroll
    for (int off = 16; off > 0; off >>= 1) {
        #pragma unroll
        for (int p = 0; p < WP; ++p) {
            su[p] += __shfl_xor_sync(0xffffffffu, su[p], off);
            sv[p] += __shfl_xor_sync(0xffffffffu, sv[p], off);
            sf[p] += __shfl_xor_sync(0xffffffffu, sf[p], off);
            sg[p] += __shfl_xor_sync(0xffffffffu, sg[p], off);
        }
    }
    if (lane == 0) {
        #pragma unroll
        for (int p = 0; p < WP; ++p) {
            int pt = base + p;
            out[0 * NPTS + pt] =  su[p];
            out[1 * NPTS + pt] = -sv[p];
            out[3 * NPTS + pt] =  sf[p];
            out[4 * NPTS + pt] =  sg[p];
        }
    }
}

extern "C" void kernel_launch(void* const* d_in, const int* in_sizes, int n_in,
                              void* d_out, int out_size)
{
    const float* x     = (const float*)d_in[0];
    const float* y     = (const float*)d_in[1];
    const float* t     = (const float*)d_in[2];
    const float* Win   = (const float*)d_in[3];
    const float* b_in  = (const float*)d_in[4];
    const float* Wh    = (const float*)d_in[5];
    const float* b_h   = (const float*)d_in[6];
    const float* Wout  = (const float*)d_in[7];
    const float* b_out = (const float*)d_in[8];
    float* out = (float*)d_out;

    prep_kernel<<<(NL * H * H) / 256, 256>>>(Wh);

    // 96KB weight triple-buffer + 8 warps * 16KB tables = 224KB
    const int smem = NBUF * CHUNK_FLOATS * (int)sizeof(float)
                   + WARPS * (256 * TROWU) * (int)sizeof(u64);
    cudaFuncSetAttribute(pinn_kernel, cudaFuncAttributeMaxDynamicSharedMemorySize, smem);
    pinn_kernel<<<NPTS / PTS_PER_CTA, THREADS, smem>>>(x, y, t, Win, b_in, Wh, b_h,
                                                       Wout, b_out, out);
}

// round 15
// speedup vs baseline: 1.2028x; 1.1014x over previous
#include <cuda_runtime.h>
#include <cuda_bf16.h>
#include <cstdint>

// NavierStokesPINN1 — ReLU MLP is piecewise linear; outputs reduce to
//   u = dpsi/dy, v = -dpsi/dx, p, f = dp/dx, g = dp/dy.
// Forward: FFMA2, bit-exact vs the reference's fp32 GEMM rounding (single
// accumulator, k ascending, fma per step, bias after reduction) -> ReLU masks
// match exactly; masks recorded in smem bitmaps, p computed directly.
// Backward: warp-level mma.sync.m16n8k16 bf16 (baseline PTX - compiles for
// compute_103, unlike tcgen05) with 2-way bf16 split (bb + bs + sb terms,
// fp32 accumulation): 4 layers of D[128x256] = A[128x256] (.) Wh[l],
// A rows = 64 points x 2 cotangent streams, masked + re-split per layer.

#define H        256
#define NL       4
#define NPTS     65536
#define WP       8
#define THREADS  256
#define WARPS    8
#define PTS_PER_CTA 64
#define CHUNK_FLOATS 8192           // fwd staging chunk: 32 rows x 256 = 32KB
#define TROWU    8                  // fwd table row stride (u64)

// smem layout (phases reuse regions; masks/win persist)
#define OFF_ABIG   0        // fwd: weight double buffer 64KB | bwd: A_big
#define OFF_ASMALL 65536    // fwd: tables 128KB @65536 | bwd: A_small 64KB
#define OFF_B      131072   // bwd: B double buffer 2 x 40960
#define BCHUNK     40960
#define OFF_MASK   212992   // 5 levels x 64 pts x 4 u64 = 10240B
#define OFF_WIN    223232   // 512 floats
#define SMEM_DYN   225280

typedef unsigned long long u64;

// Backward weights, bf16-split, chunk layout for linear staging:
// region (l*8+jc) of 40960B: big 20480 then small 20480;
// row n (0..255) stride 80B holds bf16 Wh[l][n][jc*32 .. +32) in first 64B.
__device__ __align__(16) unsigned char g_WB[NL * 8 * BCHUNK];

__device__ __forceinline__ u64 pack2(float lo, float hi) {
    u64 r; asm("mov.b64 %0, {%1, %2};" : "=l"(r) : "f"(lo), "f"(hi)); return r;
}
__device__ __forceinline__ void unpack2(u64 v, float& lo, float& hi) {
    asm("mov.b64 {%0, %1}, %2;" : "=f"(lo), "=f"(hi) : "l"(v));
}
__device__ __forceinline__ u64 ffma2(u64 a, u64 b, u64 c) {
    u64 d; asm("fma.rn.f32x2 %0, %1, %2, %3;" : "=l"(d) : "l"(a), "l"(b), "l"(c));
    return d;
}
__device__ __forceinline__ void cp_async16(void* s, const void* g) {
    unsigned sa = (unsigned)__cvta_generic_to_shared(s);
    asm volatile("cp.async.cg.shared.global [%0], [%1], 16;" :: "r"(sa), "l"(g));
}
__device__ __forceinline__ void cp_commit() { asm volatile("cp.async.commit_group;"); }
template<int NN> __device__ __forceinline__ void cp_wait() {
    asm volatile("cp.async.wait_group %0;" :: "n"(NN));
}
__device__ __forceinline__ uint32_t smem_u32(const void* p) {
    return (uint32_t)__cvta_generic_to_shared(p);
}
__device__ __forceinline__ void ldsm4(uint32_t* r, uint32_t addr) {
    asm volatile("ldmatrix.sync.aligned.m8n8.x4.shared.b16 {%0,%1,%2,%3}, [%4];"
                 : "=r"(r[0]), "=r"(r[1]), "=r"(r[2]), "=r"(r[3]) : "r"(addr));
}
__device__ __forceinline__ void mma_bf16(float* d, const uint32_t* a,
                                         uint32_t b0, uint32_t b1) {
    asm volatile(
        "mma.sync.aligned.m16n8k16.row.col.f32.bf16.bf16.f32 "
        "{%0,%1,%2,%3}, {%4,%5,%6,%7}, {%8,%9}, {%0,%1,%2,%3};"
        : "+f"(d[0]), "+f"(d[1]), "+f"(d[2]), "+f"(d[3])
        : "r"(a[0]), "r"(a[1]), "r"(a[2]), "r"(a[3]), "r"(b0), "r"(b1));
}
__device__ __forceinline__ uint32_t packbf(__nv_bfloat16 lo, __nv_bfloat16 hi) {
    __nv_bfloat162 t(lo, hi);
    return *reinterpret_cast<uint32_t*>(&t);
}

__device__ __forceinline__ void stage_fwd(float* dst, const float* src, int tid) {
    #pragma unroll
    for (int q = 0; q < CHUNK_FLOATS / 4 / THREADS; ++q) {
        int fi = q * THREADS + tid;
        cp_async16(((float4*)dst) + fi, ((const float4*)src) + fi);
    }
    cp_commit();
}

__global__ void prep_kernel(const float* __restrict__ Wh) {
    int i = blockIdx.x * blockDim.x + threadIdx.x;   // l, n(=k), j over NL*H*H
    int l = i >> 16, n = (i >> 8) & 255, j = i & 255;
    float w = __ldg(Wh + i);
    __nv_bfloat16 big = __float2bfloat16(w);
    __nv_bfloat16 sml = __float2bfloat16(w - __bfloat162float(big));
    int jc = j >> 5, kk = j & 31;
    size_t off = (size_t)(l * 8 + jc) * BCHUNK + n * 80 + kk * 2;
    *(__nv_bfloat16*)(g_WB + off)         = big;
    *(__nv_bfloat16*)(g_WB + off + 20480) = sml;
}

// lane owns neurons j = 128*(ln>>2) + 4*lane + (ln&3)
#define JN(ln) ((((ln) >> 2) << 7) + (lane << 2) + ((ln) & 3))
#define MB(pt, ln) ((u64)1 << (((pt) << 3) + (ln)))

// pack per-thread forward mask u64 into shared bitmaps (level lvl):
// maskS[(lvl*64 + pt)*4 + (j>>6)] bit (j&63)
__device__ __forceinline__ void mask_write(u64* maskS, int lvl, int warp, int lane, u64 Ml) {
    int wsel = lane >> 4;
    int sh = 4 * (lane & 15);
    #pragma unroll
    for (int p = 0; p < 8; ++p) {
        #pragma unroll
        for (int g = 0; g < 2; ++g) {
            u64 nib = (Ml >> ((p << 3) + (g << 2))) & 0xF;
            if (nib)
                atomicOr(&maskS[((lvl << 6) + (warp << 3) + p) * 4 + 2 * g + wsel],
                         nib << sh);
        }
    }
}

__global__ void __launch_bounds__(THREADS, 1)
pinn_kernel(const float* __restrict__ x, const float* __restrict__ y,
            const float* __restrict__ t,
            const float* __restrict__ Win,  const float* __restrict__ b_in,
            const float* __restrict__ Wh,   const float* __restrict__ b_h,
            const float* __restrict__ Wout, const float* __restrict__ b_out,
            float* __restrict__ out)
{
    extern __shared__ __align__(16) unsigned char smem8[];
    float* Ws = (float*)smem8;
    u64* maskS = (u64*)(smem8 + OFF_MASK);
    float* winS = (float*)(smem8 + OFF_WIN);
    const int tid  = threadIdx.x;
    const int lane = tid & 31;
    const int warp = tid >> 5;
    const int base = blockIdx.x * PTS_PER_CTA + warp * WP;

    for (int i = tid; i < 1280; i += THREADS) maskS[i] = 0ull;
    for (int i = tid; i < 512; i += THREADS) winS[i] = __ldg(Win + i);
    __syncthreads();

    stage_fwd(Ws, Wh, tid);   // forward chunk 0

    u64* tab = (u64*)(smem8 + OFF_ASMALL) + (size_t)warp * (256 * TROWU);

    // ---------------- input layer (exact GEMM rounding order) ----------------
    {
        u64 Mi = 0;
        float rx[WP], ry[WP], rt[WP];
        #pragma unroll
        for (int p = 0; p < WP; ++p) {
            rx[p] = x[base + p]; ry[p] = y[base + p]; rt[p] = t[base + p];
        }
        #pragma unroll
        for (int ln = 0; ln < 8; ++ln) {
            int j = JN(ln);
            float w0 = __ldg(Win + j);
            float w1 = __ldg(Win + H + j);
            float w2 = __ldg(Win + 2 * H + j);
            float bb = __ldg(b_in + j);
            #pragma unroll
            for (int p = 0; p < WP; ++p) {
                float acc = fmaf(rx[p], w0, 0.f);
                acc = fmaf(ry[p], w1, acc);
                acc = fmaf(rt[p], w2, acc);
                float a = acc + bb;
                bool m = a > 0.f;
                Mi |= m ? MB(p, ln) : 0ull;
                float hv = m ? a : 0.f;
                tab[j * TROWU + p] = pack2(hv, hv);
            }
        }
        mask_write(maskS, 4, warp, lane, Mi);   // level 4 = input-layer masks
    }
    __syncwarp();

    // ---------------- forward hidden layers (bit-exact FFMA2) ----------------
    float pp[WP];
    #pragma unroll
    for (int p = 0; p < WP; ++p) pp[p] = 0.f;
    int c = 0;

    #pragma unroll 1
    for (int l = 0; l < NL; ++l) {
        u64 acc[WP][4];
        #pragma unroll
        for (int p = 0; p < WP; ++p)
            #pragma unroll
            for (int np = 0; np < 4; ++np) acc[p][np] = 0ull;

        #pragma unroll 2
        for (int r = 0; r < 8; ++r, ++c) {
            if (c + 1 < 32) {
                stage_fwd(Ws + ((c + 1) & 1) * CHUNK_FLOATS,
                          Wh + (size_t)(c + 1) * CHUNK_FLOATS, tid);
                cp_wait<1>();
            } else {
                cp_wait<0>();
            }
            __syncthreads();

            const float* wb = Ws + (c & 1) * CHUNK_FLOATS + (lane << 2);
            const u64* tf = tab + (r << 5) * TROWU;
            #pragma unroll 4
            for (int kl = 0; kl < 32; ++kl) {
                ulonglong2 WA = *(const ulonglong2*)(wb + kl * H);
                ulonglong2 WB = *(const ulonglong2*)(wb + kl * H + 128);
                const ulonglong2* tr = (const ulonglong2*)(tf + kl * TROWU);
                ulonglong2 T0 = tr[0];
                ulonglong2 T1 = tr[1];
                ulonglong2 T2 = tr[2];
                ulonglong2 T3 = tr[3];
                acc[0][0] = ffma2(T0.x, WA.x, acc[0][0]);
                acc[0][1] = ffma2(T0.x, WA.y, acc[0][1]);
                acc[0][2] = ffma2(T0.x, WB.x, acc[0][2]);
                acc[0][3] = ffma2(T0.x, WB.y, acc[0][3]);
                acc[1][0] = ffma2(T0.y, WA.x, acc[1][0]);
                acc[1][1] = ffma2(T0.y, WA.y, acc[1][1]);
                acc[1][2] = ffma2(T0.y, WB.x, acc[1][2]);
                acc[1][3] = ffma2(T0.y, WB.y, acc[1][3]);
                acc[2][0] = ffma2(T1.x, WA.x, acc[2][0]);
                acc[2][1] = ffma2(T1.x, WA.y, acc[2][1]);
                acc[2][2] = ffma2(T1.x, WB.x, acc[2][2]);
                acc[2][3] = ffma2(T1.x, WB.y, acc[2][3]);
                acc[3][0] = ffma2(T1.y, WA.x, acc[3][0]);
                acc[3][1] = ffma2(T1.y, WA.y, acc[3][1]);
                acc[3][2] = ffma2(T1.y, WB.x, acc[3][2]);
                acc[3][3] = ffma2(T1.y, WB.y, acc[3][3]);
                acc[4][0] = ffma2(T2.x, WA.x, acc[4][0]);
                acc[4][1] = ffma2(T2.x, WA.y, acc[4][1]);
                acc[4][2] = ffma2(T2.x, WB.x, acc[4][2]);
                acc[4][3] = ffma2(T2.x, WB.y, acc[4][3]);
                acc[5][0] = ffma2(T2.y, WA.x, acc[5][0]);
                acc[5][1] = ffma2(T2.y, WA.y, acc[5][1]);
                acc[5][2] = ffma2(T2.y, WB.x, acc[5][2]);
                acc[5][3] = ffma2(T2.y, WB.y, acc[5][3]);
                acc[6][0] = ffma2(T3.x, WA.x, acc[6][0]);
                acc[6][1] = ffma2(T3.x, WA.y, acc[6][1]);
                acc[6][2] = ffma2(T3.x, WB.x, acc[6][2]);
                acc[6][3] = ffma2(T3.x, WB.y, acc[6][3]);
                acc[7][0] = ffma2(T3.y, WA.x, acc[7][0]);
                acc[7][1] = ffma2(T3.y, WA.y, acc[7][1]);
                acc[7][2] = ffma2(T3.y, WB.x, acc[7][2]);
                acc[7][3] = ffma2(T3.y, WB.y, acc[7][3]);
            }
            __syncthreads();
        }

        // epilogue: bias AFTER reduction, relu, record mask level l
        u64 Ml = 0;
        #pragma unroll
        for (int np = 0; np < 4; ++np) {
            int ln0 = 2 * np;
            int j0 = JN(ln0);
            float bb0 = __ldg(b_h + l * H + j0);
            float bb1 = __ldg(b_h + l * H + j0 + 1);
            if (l < NL - 1) {
                #pragma unroll
                for (int p = 0; p < WP; ++p) {
                    float a0, a1; unpack2(acc[p][np], a0, a1);
                    float v0 = a0 + bb0, v1 = a1 + bb1;
                    bool m0 = v0 > 0.f, m1 = v1 > 0.f;
                    Ml |= (m0 ? MB(p, ln0) : 0ull) | (m1 ? MB(p, ln0 + 1) : 0ull);
                    tab[j0 * TROWU + p]       = pack2(m0 ? v0 : 0.f, m0 ? v0 : 0.f);
                    tab[(j0 + 1) * TROWU + p] = pack2(m1 ? v1 : 0.f, m1 ? v1 : 0.f);
                }
            } else {
                float wo10 = __ldg(Wout + 2 * j0 + 1);
                float wo11 = __ldg(Wout + 2 * (j0 + 1) + 1);
                #pragma unroll
                for (int p = 0; p < WP; ++p) {
                    float a0, a1; unpack2(acc[p][np], a0, a1);
                    float v0 = a0 + bb0, v1 = a1 + bb1;
                    bool m0 = v0 > 0.f, m1 = v1 > 0.f;
                    Ml |= (m0 ? MB(p, ln0) : 0ull) | (m1 ? MB(p, ln0 + 1) : 0ull);
                    pp[p] = fmaf(m0 ? v0 : 0.f, wo10, pp[p]);
                    pp[p] = fmaf(m1 ? v1 : 0.f, wo11, pp[p]);
                }
            }
        }
        mask_write(maskS, l, warp, lane, Ml);
        __syncwarp();
    }

    // p output
    #pragma unroll
    for (int off = 16; off > 0; off >>= 1)
        #pragma unroll
        for (int p = 0; p < WP; ++p)
            pp[p] += __shfl_xor_sync(0xffffffffu, pp[p], off);
    if (lane == 0) {
        float bo1 = __ldg(b_out + 1);
        #pragma unroll
        for (int p = 0; p < WP; ++p)
            out[2 * NPTS + base + p] = pp[p] + bo1;
    }

    __syncthreads();   // forward done; regions become A/B

    // ---------------- A init: masked layer-3 cotangents, bf16 split ----------------
    // A[m][j]: m = s*64 + pt (s=0 psi, s=1 p), value = mask3 ? Wout[2j+s] : 0
    // A smem: element (m,k') at byte m*512 + (((k'>>3) ^ (m&7))<<4) + (k'&7)*2
    for (int idx = tid; idx < 128 * 128; idx += THREADS) {
        int m = idx >> 7, j = (idx & 127) << 1;
        int s = m >> 6, pt = m & 63;
        u64 mw = maskS[(3 * 64 + pt) * 4 + (j >> 6)];
        float v0 = ((mw >> (j & 63)) & 1) ? __ldg(Wout + 2 * j + s) : 0.f;
        float v1 = ((mw >> ((j + 1) & 63)) & 1) ? __ldg(Wout + 2 * (j + 1) + s) : 0.f;
        __nv_bfloat16 b0 = __float2bfloat16(v0), b1 = __float2bfloat16(v1);
        __nv_bfloat16 s0 = __float2bfloat16(v0 - __bfloat162float(b0));
        __nv_bfloat16 s1 = __float2bfloat16(v1 - __bfloat162float(b1));
        uint32_t off = (uint32_t)(m * 512 + (((j >> 3) ^ (m & 7)) << 4) + (j & 7) * 2);
        *(uint32_t*)(smem8 + OFF_ABIG + off)   = packbf(b0, b1);
        *(uint32_t*)(smem8 + OFF_ASMALL + off) = packbf(s0, s1);
    }

    // stage backward B chunk 0
    {
        const float4* src = (const float4*)(g_WB + (size_t)(3 * 8 + 0) * BCHUNK);
        float4* dst = (float4*)(smem8 + OFF_B);
        #pragma unroll
        for (int q = 0; q < 10; ++q)
            cp_async16(dst + q * THREADS + tid, src + q * THREADS + tid);
        cp_commit();
    }

    // ---------------- backward: mma.sync bf16, 4 layers x 8 chunks ----------------
    const uint32_t sb = smem_u32(smem8);
    const int m0 = warp * 16;
    const int i8 = lane & 7, gg = lane >> 3;
    const int mA = m0 + i8 + ((gg & 1) << 3);
    const uint32_t aBaseT = sb + (uint32_t)mA * 512u;
    const int xorm = mA & 7;
    const int kgsel = gg >> 1;
    const uint32_t bRowT = (uint32_t)((i8 + ((gg >> 1) << 3)) * 80 + ((gg & 1) << 4));

    float d[128];

    #pragma unroll 1
    for (int c2 = 0; c2 < 32; ++c2) {
        const int bl = 3 - (c2 >> 3), jc = c2 & 7;
        cp_wait<0>();
        __syncthreads();

        if (c2 + 1 < 32) {
            int nb = 3 - ((c2 + 1) >> 3), nj = (c2 + 1) & 7;
            const float4* src = (const float4*)(g_WB + (size_t)(nb * 8 + nj) * BCHUNK);
            float4* dst = (float4*)(smem8 + OFF_B + ((c2 + 1) & 1) * BCHUNK);
            #pragma unroll
            for (int q = 0; q < 10; ++q)
                cp_async16(dst + q * THREADS + tid, src + q * THREADS + tid);
            cp_commit();
        }

        if (jc == 0) {
            #pragma unroll
            for (int i = 0; i < 128; ++i) d[i] = 0.f;
        }

        const uint32_t bbase = sb + OFF_B + (uint32_t)((c2 & 1) * BCHUNK);
        #pragma unroll
        for (int st = 0; st < 2; ++st) {
            int ku = (jc << 2) + (st << 1) + kgsel;
            uint32_t aoff = (uint32_t)((ku ^ xorm) << 4);
            uint32_t ab[4], as4[4];
            ldsm4(ab, aBaseT + aoff);
            ldsm4(as4, aBaseT + 65536u + aoff);
            #pragma unroll
            for (int np2 = 0; np2 < 8; ++np2) {
                uint32_t ba = bbase + (uint32_t)(np2 * 2560 + st * 32) + bRowT;
                uint32_t bb[4], bb2[4], bs[4], bs2[4];
                ldsm4(bb, ba);
                ldsm4(bb2, ba + 1280u);
                ldsm4(bs, ba + 20480u);
                ldsm4(bs2, ba + 21760u);
                float* dd = d + np2 * 16;
                mma_bf16(dd + 0,  ab,  bb[0],  bb[1]);
                mma_bf16(dd + 4,  ab,  bb[2],  bb[3]);
                mma_bf16(dd + 8,  ab,  bb2[0], bb2[1]);
                mma_bf16(dd + 12, ab,  bb2[2], bb2[3]);
                mma_bf16(dd + 0,  ab,  bs[0],  bs[1]);
                mma_bf16(dd + 4,  ab,  bs[2],  bs[3]);
                mma_bf16(dd + 8,  ab,  bs2[0], bs2[1]);
                mma_bf16(dd + 12, ab,  bs2[2], bs2[3]);
                mma_bf16(dd + 0,  as4, bb[0],  bb[1]);
                mma_bf16(dd + 4,  as4, bb[2],  bb[3]);
                mma_bf16(dd + 8,  as4, bb2[0], bb2[1]);
                mma_bf16(dd + 12, as4, bb2[2], bb2[3]);
            }
        }

        if (jc == 7) {
            const int rA = m0 + (lane >> 2), rB = rA + 8;
            const int nc0 = 2 * (lane & 3);
            if (bl > 0) {
                // mask by level bl-1, re-split, write own A rows
                const u64* mrA = maskS + ((bl - 1) * 64 + (rA & 63)) * 4;
                const u64* mrB = maskS + ((bl - 1) * 64 + (rB & 63)) * 4;
                #pragma unroll
                for (int nt = 0; nt < 32; ++nt) {
                    int n = nt * 8 + nc0;
                    u64 mwA = mrA[nt >> 3], mwB = mrB[nt >> 3];
                    float vA0 = ((mwA >> (n & 63)) & 1) ? d[nt * 4 + 0] : 0.f;
                    float vA1 = ((mwA >> ((n + 1) & 63)) & 1) ? d[nt * 4 + 1] : 0.f;
                    float vB0 = ((mwB >> (n & 63)) & 1) ? d[nt * 4 + 2] : 0.f;
                    float vB1 = ((mwB >> ((n + 1) & 63)) & 1) ? d[nt * 4 + 3] : 0.f;
                    __nv_bfloat16 bA0 = __float2bfloat16(vA0), bA1 = __float2bfloat16(vA1);
                    __nv_bfloat16 bB0 = __float2bfloat16(vB0), bB1 = __float2bfloat16(vB1);
                    __nv_bfloat16 sA0 = __float2bfloat16(vA0 - __bfloat162float(bA0));
                    __nv_bfloat16 sA1 = __float2bfloat16(vA1 - __bfloat162float(bA1));
                    __nv_bfloat16 sB0 = __float2bfloat16(vB0 - __bfloat162float(bB0));
                    __nv_bfloat16 sB1 = __float2bfloat16(vB1 - __bfloat162float(bB1));
                    uint32_t offA = (uint32_t)(rA * 512 + (((n >> 3) ^ (rA & 7)) << 4) + (n & 7) * 2);
                    uint32_t offB = (uint32_t)(rB * 512 + (((n >> 3) ^ (rB & 7)) << 4) + (n & 7) * 2);
                    *(uint32_t*)(smem8 + OFF_ABIG + offA)   = packbf(bA0, bA1);
                    *(uint32_t*)(smem8 + OFF_ASMALL + offA) = packbf(sA0, sA1);
                    *(uint32_t*)(smem8 + OFF_ABIG + offB)   = packbf(bB0, bB1);
                    *(uint32_t*)(smem8 + OFF_ASMALL + offB) = packbf(sB0, sB1);
                }
            } else {
                // final: mask by input level (4), dot with Win rows -> u,v,f,g
                const u64* mrA = maskS + (4 * 64 + (rA & 63)) * 4;
                const u64* mrB = maskS + (4 * 64 + (rB & 63)) * 4;
                float dxA = 0.f, dyA = 0.f, dxB = 0.f, dyB = 0.f;
                #pragma unroll
                for (int nt = 0; nt < 32; ++nt) {
                    int n = nt * 8 + nc0;
                    u64 mwA = mrA[nt >> 3], mwB = mrB[nt >> 3];
                    float vA0 = ((mwA >> (n & 63)) & 1) ? d[nt * 4 + 0] : 0.f;
                    float vA1 = ((mwA >> ((n + 1) & 63)) & 1) ? d[nt * 4 + 1] : 0.f;
                    float vB0 = ((mwB >> (n & 63)) & 1) ? d[nt * 4 + 2] : 0.f;
                    float vB1 = ((mwB >> ((n + 1) & 63)) & 1) ? d[nt * 4 + 3] : 0.f;
                    float wx0 = winS[n], wx1 = winS[n + 1];
                    float wy0 = winS[256 + n], wy1 = winS[256 + n + 1];
                    dxA = fmaf(wx0, vA0, dxA); dxA = fmaf(wx1, vA1, dxA);
                    dyA = fmaf(wy0, vA0, dyA); dyA = fmaf(wy1, vA1, dyA);
                    dxB = fmaf(wx0, vB0, dxB); dxB = fmaf(wx1, vB1, dxB);
                    dyB = fmaf(wy0, vB0, dyB); dyB = fmaf(wy1, vB1, dyB);
                }
                #pragma unroll
                for (int o = 1; o <= 2; o <<= 1) {
                    dxA += __shfl_xor_sync(0xffffffffu, dxA, o);
                    dyA += __shfl_xor_sync(0xffffffffu, dyA, o);
                    dxB += __shfl_xor_sync(0xffffffffu, dxB, o);
                    dyB += __shfl_xor_sync(0xffffffffu, dyB, o);
                }
                if ((lane & 3) == 0) {
                    int sA = rA >> 6, ptA = rA & 63;
                    int gA = blockIdx.x * PTS_PER_CTA + ptA;
                    if (sA == 0) { out[0 * NPTS + gA] = dyA; out[1 * NPTS + gA] = -dxA; }
                    else         { out[3 * NPTS + gA] = dxA; out[4 * NPTS + gA] = dyA; }
                    int sB = rB >> 6, ptB = rB & 63;
                    int gB = blockIdx.x * PTS_PER_CTA + ptB;
                    if (sB == 0) { out[0 * NPTS + gB] = dyB; out[1 * NPTS + gB] = -dxB; }
                    else         { out[3 * NPTS + gB] = dxB; out[4 * NPTS + gB] = dyB; }
                }
            }
        }
    }
}

extern "C" void kernel_launch(void* const* d_in, const int* in_sizes, int n_in,
                              void* d_out, int out_size)
{
    const float* x     = (const float*)d_in[0];
    const float* y     = (const float*)d_in[1];
    const float* t     = (const float*)d_in[2];
    const float* Win   = (const float*)d_in[3];
    const float* b_in  = (const float*)d_in[4];
    const float* Wh    = (const float*)d_in[5];
    const float* b_h   = (const float*)d_in[6];
    const float* Wout  = (const float*)d_in[7];
    const float* b_out = (const float*)d_in[8];
    float* out = (float*)d_out;

    prep_kernel<<<(NL * H * H) / 256, 256>>>(Wh);

    cudaFuncSetAttribute(pinn_kernel, cudaFuncAttributeMaxDynamicSharedMemorySize,
                         SMEM_DYN);
    pinn_kernel<<<NPTS / PTS_PER_CTA, THREADS, SMEM_DYN>>>(
        x, y, t, Win, b_in, Wh, b_h, Wout, b_out, out);
}